// round 7
// baseline (speedup 1.0000x reference)
#include <cuda_runtime.h>

#define B_  4
#define L_  100
#define BL_ 400           // B*L
#define DM_ 128           // d_model
#define DI_ 256           // d_inner
#define DS_ 256           // d_state
#define NQD 16            // d-chunks in k_main (16 d's each)

// scratch (device globals; no allocations allowed)
__device__ float g_xpre[BL_ * DI_];
__device__ float g_x   [BL_ * DI_];
__device__ float g_z   [BL_ * DI_];
__device__ float g_Bm  [BL_ * DS_];
__device__ float g_dt  [BL_ * DI_];
__device__ float g_ypart[NQD * BL_ * DS_];  // partial y per d-chunk
__device__ float g_negA[DI_ * DS_];
// transposed weights: tW[k*N + n] = W[n*K + k]
__device__ float g_tinW [DM_ * 512];   // 128 x 512
__device__ float g_txW  [DI_ * DS_];   // 256 x 256 (first DS rows of x_proj_w)
__device__ float g_tdtW [DI_ * DI_];   // 256 x 256
__device__ float g_toutW[DI_ * DM_];   // 256 x 128

// ---------------------------------------------------------------------------
// transpose the 4 weight matrices (blockIdx.y selects matrix)
__global__ void k_transpose(const float* __restrict__ inW,
                            const float* __restrict__ xW,
                            const float* __restrict__ dtW,
                            const float* __restrict__ outW) {
    __shared__ float tile[32][33];
    const float* src; float* dst; int R, Ccol;   // src is R x Ccol
    switch (blockIdx.y) {
        case 0: src = inW;  dst = g_tinW;  R = 512; Ccol = DM_; break;
        case 1: src = xW;   dst = g_txW;   R = DS_; Ccol = DI_; break;
        case 2: src = dtW;  dst = g_tdtW;  R = DI_; Ccol = DI_; break;
        default:src = outW; dst = g_toutW; R = DM_; Ccol = DI_; break;
    }
    int tilesX = Ccol >> 5;
    int tx = blockIdx.x % tilesX;
    int ty = blockIdx.x / tilesX;
    if (ty >= (R >> 5)) return;
    int c = tx * 32 + threadIdx.x;
    int r = ty * 32 + threadIdx.y;
    #pragma unroll
    for (int j = 0; j < 32; j += 8)
        tile[threadIdx.y + j][threadIdx.x] = src[(r + j) * Ccol + c];
    __syncthreads();
    int oc = ty * 32 + threadIdx.x;
    int orow = tx * 32 + threadIdx.y;
    #pragma unroll
    for (int j = 0; j < 32; j += 8)
        dst[(orow + j) * R + oc] = tile[threadIdx.x][threadIdx.y + j];
}

// ---------------------------------------------------------------------------
__global__ void k_negA(const float* __restrict__ A_log) {
    int i = blockIdx.x * 256 + threadIdx.x;
    g_negA[i] = -__expf(A_log[i]);
}

// ---------------------------------------------------------------------------
// in_proj: grid (100 rowtiles, 4 colgroups), 128 threads (one col each)
__global__ void k_inproj(const float* __restrict__ hs,
                         const float* __restrict__ bias) {
    __shared__ float sh[4][DM_];
    int r0 = blockIdx.x * 4;
    int cg = blockIdx.y;
    int t  = threadIdx.x;            // 0..127
    #pragma unroll
    for (int r = 0; r < 4; r++)
        sh[r][t] = hs[(r0 + r) * DM_ + t];
    __syncthreads();

    int col = cg * 128 + t;          // 0..511
    float a0 = 0.f, a1 = 0.f, a2 = 0.f, a3 = 0.f;
    #pragma unroll 16
    for (int k = 0; k < DM_; k++) {
        float wv = g_tinW[k * 512 + col];
        a0 = fmaf(wv, sh[0][k], a0);
        a1 = fmaf(wv, sh[1][k], a1);
        a2 = fmaf(wv, sh[2][k], a2);
        a3 = fmaf(wv, sh[3][k], a3);
    }
    float bv = __ldg(bias + col);
    a0 += bv; a1 += bv; a2 += bv; a3 += bv;
    if (col < DI_) {
        g_xpre[(r0 + 0) * DI_ + col] = a0;
        g_xpre[(r0 + 1) * DI_ + col] = a1;
        g_xpre[(r0 + 2) * DI_ + col] = a2;
        g_xpre[(r0 + 3) * DI_ + col] = a3;
    } else {
        int j = col - DI_;
        g_z[(r0 + 0) * DI_ + j] = a0;
        g_z[(r0 + 1) * DI_ + j] = a1;
        g_z[(r0 + 2) * DI_ + j] = a2;
        g_z[(r0 + 3) * DI_ + j] = a3;
    }
}

// ---------------------------------------------------------------------------
// fused conv+silu (recomputed per colgroup; only cg0 writes g_x) then
// Bm / softplus-dt GEMM. grid (100 rowtiles, 4 colgroups), 128 threads.
__global__ void k_convxproj(const float* __restrict__ cw,
                            const float* __restrict__ cb,
                            const float* __restrict__ dtb) {
    __shared__ float sx[4][DI_];
    int r0 = blockIdx.x * 4;
    int cg = blockIdx.y;
    int b  = r0 / L_;
    int l0 = r0 - b * L_;
    int t  = threadIdx.x;            // 0..127

    #pragma unroll
    for (int i = t; i < 4 * DI_; i += 128) {
        int r = i >> 8, c = i & 255;
        int l = l0 + r;
        float acc = __ldg(cb + c);
        #pragma unroll
        for (int j = 0; j < 4; j++) {
            int ll = l - 3 + j;
            if (ll >= 0)
                acc = fmaf(__ldg(cw + c * 4 + j), g_xpre[(b * L_ + ll) * DI_ + c], acc);
        }
        float sg = 1.f / (1.f + __expf(-acc));
        float xv = acc * sg;
        sx[r][c] = xv;
        if (cg == 0) g_x[(r0 + r) * DI_ + c] = xv;
    }
    __syncthreads();

    int col = cg * 128 + t;          // 0..511
    const float* wr = (col < DS_) ? (g_txW + col) : (g_tdtW + (col - DS_));
    float a0 = 0.f, a1 = 0.f, a2 = 0.f, a3 = 0.f;
    #pragma unroll 16
    for (int k = 0; k < DI_; k++) {
        float wv = wr[k * DI_];
        a0 = fmaf(wv, sx[0][k], a0);
        a1 = fmaf(wv, sx[1][k], a1);
        a2 = fmaf(wv, sx[2][k], a2);
        a3 = fmaf(wv, sx[3][k], a3);
    }
    if (col < DS_) {
        g_Bm[(r0 + 0) * DS_ + col] = a0;
        g_Bm[(r0 + 1) * DS_ + col] = a1;
        g_Bm[(r0 + 2) * DS_ + col] = a2;
        g_Bm[(r0 + 3) * DS_ + col] = a3;
    } else {
        int j = col - DS_;
        float bv = __ldg(dtb + j);
        float v, sp;
        v = a0 + bv; sp = (v > 15.f) ? v : log1pf(__expf(v)); g_dt[(r0 + 0) * DI_ + j] = sp;
        v = a1 + bv; sp = (v > 15.f) ? v : log1pf(__expf(v)); g_dt[(r0 + 1) * DI_ + j] = sp;
        v = a2 + bv; sp = (v > 15.f) ? v : log1pf(__expf(v)); g_dt[(r0 + 2) * DI_ + j] = sp;
        v = a3 + bv; sp = (v > 15.f) ? v : log1pf(__expf(v)); g_dt[(r0 + 3) * DI_ + j] = sp;
    }
}

// ---------------------------------------------------------------------------
// main: 1600 blocks = (l, qd); each block does ALL 4 batches so C/negA float4s
// load once into registers and serve 4 uses (L2 traffic 420->256 MB).
// 256 threads = 4 d-subgroups x 64 float4 n-lanes; 4 d's per subgroup.
__global__ void __launch_bounds__(256, 4) k_main(
        const float* __restrict__ state,
        const float* __restrict__ C,
        float*       __restrict__ out_state) {
    int bid = blockIdx.x;
    int qd = bid & (NQD - 1);
    int l  = bid >> 4;                // 0..99
    int t  = threadIdx.x;             // 0..255
    int sub = t >> 6;                 // 0..3
    int nq  = t & 63;                 // float4 lane over n

    __shared__ float  sdt[4][16];
    __shared__ float4 sbm[4][64];
    if (t < 64) {
        int b = t >> 4, dd = t & 15;
        sdt[b][dd] = g_dt[(b * L_ + l) * DI_ + qd * 16 + dd];
    }
    sbm[sub][nq] = ((const float4*)(g_Bm + (size_t)(sub * L_ + l) * DS_))[nq];
    __syncthreads();

    int d0 = qd * 16 + sub * 4;
    float4 acc[4];
    #pragma unroll
    for (int b = 0; b < 4; b++) acc[b] = make_float4(0.f, 0.f, 0.f, 0.f);

    #pragma unroll
    for (int dd = 0; dd < 4; dd++) {
        int d = d0 + dd;
        float4 na = __ldg((const float4*)(g_negA + (size_t)d * DS_) + nq);
        float4 c  = __ldg((const float4*)(C + ((size_t)l * DI_ + d) * DS_) + nq);
        #pragma unroll
        for (int b = 0; b < 4; b++) {
            size_t row = ((size_t)(b * L_ + l) * DI_ + d) * DS_;
            float4 s  = __ldcs((const float4*)(state + row) + nq);
            float  dt = sdt[b][sub * 4 + dd];
            float4 bm = sbm[b][nq];
            float4 as;
            as.x = fmaf(s.x, __expf(dt * na.x), dt * bm.x);
            as.y = fmaf(s.y, __expf(dt * na.y), dt * bm.y);
            as.z = fmaf(s.z, __expf(dt * na.z), dt * bm.z);
            as.w = fmaf(s.w, __expf(dt * na.w), dt * bm.w);
            __stcs((float4*)(out_state + row) + nq, as);
            acc[b].x = fmaf(as.x, c.x, acc[b].x);
            acc[b].y = fmaf(as.y, c.y, acc[b].y);
            acc[b].z = fmaf(as.z, c.z, acc[b].z);
            acc[b].w = fmaf(as.w, c.w, acc[b].w);
        }
    }

    __shared__ float4 racc[4][4][64];
    #pragma unroll
    for (int b = 0; b < 4; b++) racc[sub][b][nq] = acc[b];
    __syncthreads();

    {
        int bb = sub;                 // reuse 256 threads as (batch, lane)
        float4 a0 = racc[0][bb][nq], a1 = racc[1][bb][nq],
               a2 = racc[2][bb][nq], a3 = racc[3][bb][nq];
        float4 tot;
        tot.x = (a0.x + a1.x) + (a2.x + a3.x);
        tot.y = (a0.y + a1.y) + (a2.y + a3.y);
        tot.z = (a0.z + a1.z) + (a2.z + a3.z);
        tot.w = (a0.w + a1.w) + (a2.w + a3.w);
        ((float4*)(g_ypart + ((size_t)qd * BL_ + bb * L_ + l) * DS_))[nq] = tot;
    }
}

// ---------------------------------------------------------------------------
// out = y @ out_proj_w^T + b with fused epilogue. grid (100, 2 colgroups),
// 128 threads: col = cg*64 + (t&63), k-half = t>>6.
__global__ void k_outproj(const float* __restrict__ D1,
                          const float* __restrict__ bias,
                          float* __restrict__ out) {
    __shared__ float sh[4][DI_];
    __shared__ float spart[2][4][64];
    int r0 = blockIdx.x * 4;
    int cg = blockIdx.y;
    int t  = threadIdx.x;            // 0..127
    int col = cg * 64 + (t & 63);
    int kh  = t >> 6;

    for (int i = t; i < 4 * DI_; i += 128) {
        int r = i >> 8, k = i & 255;
        int idx = (r0 + r) * DI_ + k;
        float tot = 0.f;
        #pragma unroll
        for (int qq = 0; qq < NQD; qq++)
            tot += g_ypart[qq * (BL_ * DS_) + idx];
        float xv = g_x[idx];
        float zv = g_z[idx];
        float y  = fmaf(__ldg(D1 + k), xv, tot);
        float sg = 1.f / (1.f + __expf(-zv));
        sh[r][k] = y * (zv * sg);
    }
    __syncthreads();

    float a0 = 0.f, a1 = 0.f, a2 = 0.f, a3 = 0.f;
    int kbase = kh * 128;
    #pragma unroll 16
    for (int kk = 0; kk < 128; kk++) {
        int k = kbase + kk;
        float wv = g_toutW[k * DM_ + col];
        a0 = fmaf(wv, sh[0][k], a0);
        a1 = fmaf(wv, sh[1][k], a1);
        a2 = fmaf(wv, sh[2][k], a2);
        a3 = fmaf(wv, sh[3][k], a3);
    }
    spart[kh][0][t & 63] = a0;
    spart[kh][1][t & 63] = a1;
    spart[kh][2][t & 63] = a2;
    spart[kh][3][t & 63] = a3;
    __syncthreads();

    if (kh == 0) {
        int j = t & 63;
        float bv = __ldg(bias + col);
        out[(r0 + 0) * DM_ + col] = spart[0][0][j] + spart[1][0][j] + bv;
        out[(r0 + 1) * DM_ + col] = spart[0][1][j] + spart[1][1][j] + bv;
        out[(r0 + 2) * DM_ + col] = spart[0][2][j] + spart[1][2][j] + bv;
        out[(r0 + 3) * DM_ + col] = spart[0][3][j] + spart[1][3][j] + bv;
    }
}

// ---------------------------------------------------------------------------
extern "C" void kernel_launch(void* const* d_in, const int* in_sizes, int n_in,
                              void* d_out, int out_size) {
    const float* hs      = (const float*)d_in[0];   // (4,100,128)
    const float* state   = (const float*)d_in[1];   // (4,100,256,256)
    const float* inW     = (const float*)d_in[2];   // (512,128)
    const float* inB     = (const float*)d_in[3];   // (512,)
    const float* convW   = (const float*)d_in[4];   // (256,1,4)
    const float* convB   = (const float*)d_in[5];   // (256,)
    const float* xW      = (const float*)d_in[6];   // (512,256)
    const float* dtW     = (const float*)d_in[7];   // (256,256)
    const float* dtB     = (const float*)d_in[8];   // (256,)
    const float* A_log   = (const float*)d_in[9];   // (256,256)
    const float* D1      = (const float*)d_in[10];  // (256,)
    const float* Cp      = (const float*)d_in[11];  // (100,256,256)
    const float* outW    = (const float*)d_in[12];  // (128,256)
    const float* outB    = (const float*)d_in[13];  // (128,)

    float* out       = (float*)d_out;               // (4,100,128) first
    float* out_state = out + B_ * L_ * DM_;         // then (4,100,256,256)

    k_transpose<<<dim3(64, 4), dim3(32, 8)>>>(inW, xW, dtW, outW);
    k_negA     <<<256, 256>>>(A_log);
    k_inproj   <<<dim3(BL_ / 4, 4), 128>>>(hs, inB);
    k_convxproj<<<dim3(BL_ / 4, 4), 128>>>(convW, convB, dtB);  // 4th (profiled)
    k_main     <<<L_ * NQD, 256>>>(state, Cp, out_state);
    k_outproj  <<<dim3(BL_ / 4, 2), 128>>>(D1, outB, out);
}

// round 8
// speedup vs baseline: 1.0632x; 1.0632x over previous
#include <cuda_runtime.h>

#define B_  4
#define L_  100
#define BL_ 400           // B*L
#define DM_ 128           // d_model
#define DI_ 256           // d_inner
#define DS_ 256           // d_state
#define NQD 32            // d-chunks in k_main (8 d's each)

// scratch (device globals; no allocations allowed)
__device__ float g_xpre[BL_ * DI_];
__device__ float g_x   [BL_ * DI_];
__device__ float g_z   [BL_ * DI_];
__device__ float g_Bm  [BL_ * DS_];
__device__ float g_dt  [BL_ * DI_];
__device__ float g_ypart[NQD * BL_ * DS_];  // partial y per d-chunk
__device__ float g_negA[DI_ * DS_];
// transposed weights: tW[k*N + n] = W[n*K + k]
__device__ float g_tinW [DM_ * 512];   // 128 x 512
__device__ float g_txW  [DI_ * DS_];   // 256 x 256 (first DS rows of x_proj_w)
__device__ float g_tdtW [DI_ * DI_];   // 256 x 256
__device__ float g_toutW[DI_ * DM_];   // 256 x 128

// ---------------------------------------------------------------------------
// prep: blockIdx.y 0..3 -> transpose one weight matrix; y==4 -> negA
__global__ void k_prep(const float* __restrict__ inW,
                       const float* __restrict__ xW,
                       const float* __restrict__ dtW,
                       const float* __restrict__ outW,
                       const float* __restrict__ A_log) {
    if (blockIdx.y == 4) {
        int tid = threadIdx.y * 32 + threadIdx.x;       // 0..255
        for (int i = blockIdx.x * 256 + tid; i < DI_ * DS_; i += 64 * 256)
            g_negA[i] = -__expf(A_log[i]);
        return;
    }
    __shared__ float tile[32][33];
    const float* src; float* dst; int R, Ccol;   // src is R x Ccol
    switch (blockIdx.y) {
        case 0: src = inW;  dst = g_tinW;  R = 512; Ccol = DM_; break;
        case 1: src = xW;   dst = g_txW;   R = DS_; Ccol = DI_; break;
        case 2: src = dtW;  dst = g_tdtW;  R = DI_; Ccol = DI_; break;
        default:src = outW; dst = g_toutW; R = DM_; Ccol = DI_; break;
    }
    int tilesX = Ccol >> 5;
    int tx = blockIdx.x % tilesX;
    int ty = blockIdx.x / tilesX;
    if (ty >= (R >> 5)) return;
    int c = tx * 32 + threadIdx.x;
    int r = ty * 32 + threadIdx.y;
    #pragma unroll
    for (int j = 0; j < 32; j += 8)
        tile[threadIdx.y + j][threadIdx.x] = src[(r + j) * Ccol + c];
    __syncthreads();
    int oc = ty * 32 + threadIdx.x;
    int orow = tx * 32 + threadIdx.y;
    #pragma unroll
    for (int j = 0; j < 32; j += 8)
        dst[(orow + j) * R + oc] = tile[threadIdx.x][threadIdx.y + j];
}

// ---------------------------------------------------------------------------
// in_proj: grid (200 rowpairs, 4 colgroups), 256 threads = 128 cols x 2 k-halves
__global__ void k_inproj(const float* __restrict__ hs,
                         const float* __restrict__ bias) {
    __shared__ float sh[2][DM_];
    __shared__ float spart[2][2][128];
    int r0 = blockIdx.x * 2;
    int cg = blockIdx.y;
    int t  = threadIdx.x;            // 0..255
    {
        int r = t >> 7, k = t & 127;
        sh[r][k] = hs[(r0 + r) * DM_ + k];
    }
    __syncthreads();

    int cl = t & 127;
    int col = cg * 128 + cl;         // 0..511
    int kh = t >> 7;                 // 0..1
    float a0 = 0.f, a1 = 0.f;
    #pragma unroll 16
    for (int kk = 0; kk < 64; kk++) {
        int k = kh * 64 + kk;
        float wv = g_tinW[k * 512 + col];
        a0 = fmaf(wv, sh[0][k], a0);
        a1 = fmaf(wv, sh[1][k], a1);
    }
    spart[kh][0][cl] = a0;
    spart[kh][1][cl] = a1;
    __syncthreads();

    if (kh == 0) {
        float bv = __ldg(bias + col);
        float v0 = spart[0][0][cl] + spart[1][0][cl] + bv;
        float v1 = spart[0][1][cl] + spart[1][1][cl] + bv;
        if (col < DI_) {
            g_xpre[(r0 + 0) * DI_ + col] = v0;
            g_xpre[(r0 + 1) * DI_ + col] = v1;
        } else {
            int j = col - DI_;
            g_z[(r0 + 0) * DI_ + j] = v0;
            g_z[(r0 + 1) * DI_ + j] = v1;
        }
    }
}

// ---------------------------------------------------------------------------
// causal depthwise conv (width 4) + bias + silu -> g_x
__global__ void k_conv(const float* __restrict__ cw,
                       const float* __restrict__ cb) {
    int bl = blockIdx.x;               // b*100 + l
    int c  = threadIdx.x;              // channel 0..255
    int b  = bl / L_;
    int l  = bl - b * L_;
    float acc = __ldg(cb + c);
    #pragma unroll
    for (int j = 0; j < 4; j++) {
        int ll = l - 3 + j;
        if (ll >= 0)
            acc = fmaf(__ldg(cw + c * 4 + j), g_xpre[(b * L_ + ll) * DI_ + c], acc);
    }
    float sg = 1.f / (1.f + __expf(-acc));
    g_x[bl * DI_ + c] = acc * sg;
}

// ---------------------------------------------------------------------------
// Bm / softplus-dt GEMM: grid (200 rowpairs, 4 colgroups),
// 256 threads = 128 cols x 2 k-halves (k=128 each)
__global__ void k_xprojdt(const float* __restrict__ dtb) {
    __shared__ float sx[2][DI_];
    __shared__ float spart[2][2][128];
    int r0 = blockIdx.x * 2;
    int cg = blockIdx.y;
    int t  = threadIdx.x;            // 0..255
    for (int i = t; i < 2 * DI_; i += 256)
        sx[i >> 8][i & 255] = g_x[(r0 + (i >> 8)) * DI_ + (i & 255)];
    __syncthreads();

    int cl = t & 127;
    int col = cg * 128 + cl;         // 0..511
    int kh = t >> 7;                 // 0..1
    const float* wr = (col < DS_) ? (g_txW + col) : (g_tdtW + (col - DS_));
    float a0 = 0.f, a1 = 0.f;
    #pragma unroll 16
    for (int kk = 0; kk < 128; kk++) {
        int k = kh * 128 + kk;
        float wv = wr[k * DI_];
        a0 = fmaf(wv, sx[0][k], a0);
        a1 = fmaf(wv, sx[1][k], a1);
    }
    spart[kh][0][cl] = a0;
    spart[kh][1][cl] = a1;
    __syncthreads();

    if (kh == 0) {
        float v0 = spart[0][0][cl] + spart[1][0][cl];
        float v1 = spart[0][1][cl] + spart[1][1][cl];
        if (col < DS_) {
            g_Bm[(r0 + 0) * DS_ + col] = v0;
            g_Bm[(r0 + 1) * DS_ + col] = v1;
        } else {
            int j = col - DS_;
            float bv = __ldg(dtb + j);
            float v, sp;
            v = v0 + bv; sp = (v > 15.f) ? v : log1pf(__expf(v)); g_dt[(r0 + 0) * DI_ + j] = sp;
            v = v1 + bv; sp = (v > 15.f) ? v : log1pf(__expf(v)); g_dt[(r0 + 1) * DI_ + j] = sp;
        }
    }
}

// ---------------------------------------------------------------------------
// main: 3200 blocks = (l, qd); each block does ALL 4 batches so C/negA float4s
// load once into registers and serve 4 uses. 256 threads = 4 d-subgroups x
// 64 float4 n-lanes; 2 d's per subgroup (8 d's per block).
__global__ void __launch_bounds__(256, 6) k_main(
        const float* __restrict__ state,
        const float* __restrict__ C,
        float*       __restrict__ out_state) {
    int bid = blockIdx.x;
    int qd = bid & (NQD - 1);
    int l  = bid >> 5;                // 0..99
    int t  = threadIdx.x;             // 0..255
    int sub = t >> 6;                 // 0..3
    int nq  = t & 63;                 // float4 lane over n

    __shared__ float  sdt[4][8];
    __shared__ float4 sbm[4][64];
    if (t < 32) {
        int b = t >> 3, dd = t & 7;
        sdt[b][dd] = g_dt[(b * L_ + l) * DI_ + qd * 8 + dd];
    }
    sbm[sub][nq] = ((const float4*)(g_Bm + (size_t)(sub * L_ + l) * DS_))[nq];
    __syncthreads();

    int d0 = qd * 8 + sub * 2;
    float4 acc[4];
    #pragma unroll
    for (int b = 0; b < 4; b++) acc[b] = make_float4(0.f, 0.f, 0.f, 0.f);

    #pragma unroll
    for (int dd = 0; dd < 2; dd++) {
        int d = d0 + dd;
        float4 na = __ldg((const float4*)(g_negA + (size_t)d * DS_) + nq);
        float4 c  = __ldg((const float4*)(C + ((size_t)l * DI_ + d) * DS_) + nq);
        #pragma unroll
        for (int b = 0; b < 4; b++) {
            size_t row = ((size_t)(b * L_ + l) * DI_ + d) * DS_;
            float4 s  = __ldcs((const float4*)(state + row) + nq);
            float  dt = sdt[b][sub * 2 + dd];
            float4 bm = sbm[b][nq];
            float4 as;
            as.x = fmaf(s.x, __expf(dt * na.x), dt * bm.x);
            as.y = fmaf(s.y, __expf(dt * na.y), dt * bm.y);
            as.z = fmaf(s.z, __expf(dt * na.z), dt * bm.z);
            as.w = fmaf(s.w, __expf(dt * na.w), dt * bm.w);
            __stcs((float4*)(out_state + row) + nq, as);
            acc[b].x = fmaf(as.x, c.x, acc[b].x);
            acc[b].y = fmaf(as.y, c.y, acc[b].y);
            acc[b].z = fmaf(as.z, c.z, acc[b].z);
            acc[b].w = fmaf(as.w, c.w, acc[b].w);
        }
    }

    __shared__ float4 racc[4][4][64];
    #pragma unroll
    for (int b = 0; b < 4; b++) racc[sub][b][nq] = acc[b];
    __syncthreads();

    {
        int bb = sub;                 // reuse 256 threads as (batch, lane)
        float4 a0 = racc[0][bb][nq], a1 = racc[1][bb][nq],
               a2 = racc[2][bb][nq], a3 = racc[3][bb][nq];
        float4 tot;
        tot.x = (a0.x + a1.x) + (a2.x + a3.x);
        tot.y = (a0.y + a1.y) + (a2.y + a3.y);
        tot.z = (a0.z + a1.z) + (a2.z + a3.z);
        tot.w = (a0.w + a1.w) + (a2.w + a3.w);
        ((float4*)(g_ypart + ((size_t)qd * BL_ + bb * L_ + l) * DS_))[nq] = tot;
    }
}

// ---------------------------------------------------------------------------
// out = y @ out_proj_w^T + b with fused epilogue. grid (200 rowpairs, 2
// colgroups), 256 threads = 64 cols x 4 k-quarters (k=64 each).
__global__ void k_outproj(const float* __restrict__ D1,
                          const float* __restrict__ bias,
                          float* __restrict__ out) {
    __shared__ float sh[2][DI_];
    __shared__ float spart[4][2][64];
    int r0 = blockIdx.x * 2;
    int cg = blockIdx.y;
    int t  = threadIdx.x;            // 0..255

    for (int i = t; i < 2 * DI_; i += 256) {
        int r = i >> 8, k = i & 255;
        int idx = (r0 + r) * DI_ + k;
        float tot = 0.f;
        #pragma unroll
        for (int qq = 0; qq < NQD; qq++)
            tot += g_ypart[qq * (BL_ * DS_) + idx];
        float xv = g_x[idx];
        float zv = g_z[idx];
        float y  = fmaf(__ldg(D1 + k), xv, tot);
        float sg = 1.f / (1.f + __expf(-zv));
        sh[r][k] = y * (zv * sg);
    }
    __syncthreads();

    int cl = t & 63;
    int col = cg * 64 + cl;          // 0..127
    int kq = t >> 6;                 // 0..3
    float a0 = 0.f, a1 = 0.f;
    #pragma unroll 16
    for (int kk = 0; kk < 64; kk++) {
        int k = kq * 64 + kk;
        float wv = g_toutW[k * DM_ + col];
        a0 = fmaf(wv, sh[0][k], a0);
        a1 = fmaf(wv, sh[1][k], a1);
    }
    spart[kq][0][cl] = a0;
    spart[kq][1][cl] = a1;
    __syncthreads();

    if (kq == 0) {
        float bv = __ldg(bias + col);
        float v0 = (spart[0][0][cl] + spart[1][0][cl]) + (spart[2][0][cl] + spart[3][0][cl]) + bv;
        float v1 = (spart[0][1][cl] + spart[1][1][cl]) + (spart[2][1][cl] + spart[3][1][cl]) + bv;
        out[(r0 + 0) * DM_ + col] = v0;
        out[(r0 + 1) * DM_ + col] = v1;
    }
}

// ---------------------------------------------------------------------------
extern "C" void kernel_launch(void* const* d_in, const int* in_sizes, int n_in,
                              void* d_out, int out_size) {
    const float* hs      = (const float*)d_in[0];   // (4,100,128)
    const float* state   = (const float*)d_in[1];   // (4,100,256,256)
    const float* inW     = (const float*)d_in[2];   // (512,128)
    const float* inB     = (const float*)d_in[3];   // (512,)
    const float* convW   = (const float*)d_in[4];   // (256,1,4)
    const float* convB   = (const float*)d_in[5];   // (256,)
    const float* xW      = (const float*)d_in[6];   // (512,256)
    const float* dtW     = (const float*)d_in[7];   // (256,256)
    const float* dtB     = (const float*)d_in[8];   // (256,)
    const float* A_log   = (const float*)d_in[9];   // (256,256)
    const float* D1      = (const float*)d_in[10];  // (256,)
    const float* Cp      = (const float*)d_in[11];  // (100,256,256)
    const float* outW    = (const float*)d_in[12];  // (128,256)
    const float* outB    = (const float*)d_in[13];  // (128,)

    float* out       = (float*)d_out;               // (4,100,128) first
    float* out_state = out + B_ * L_ * DM_;         // then (4,100,256,256)

    k_prep    <<<dim3(64, 5), dim3(32, 8)>>>(inW, xW, dtW, outW, A_log);
    k_inproj  <<<dim3(BL_ / 2, 4), 256>>>(hs, inB);
    k_conv    <<<BL_, DI_>>>(convW, convB);
    k_xprojdt <<<dim3(BL_ / 2, 4), 256>>>(dtB);     // 4th launch (profiled)
    k_main    <<<L_ * NQD, 256>>>(state, Cp, out_state);
    k_outproj <<<dim3(BL_ / 2, 2), 256>>>(D1, outB, out);
}

// round 9
// speedup vs baseline: 1.5669x; 1.4738x over previous
#include <cuda_runtime.h>

#define B_  4
#define L_  100
#define BL_ 400           // B*L
#define DM_ 128           // d_model
#define DI_ 256           // d_inner
#define DS_ 256           // d_state
#define NQD 16            // d-chunks in k_main (16 d's each)

// scratch (device globals; no allocations allowed)
__device__ float g_xpre[BL_ * DI_];
__device__ float g_x   [BL_ * DI_];
__device__ float g_z   [BL_ * DI_];
__device__ float g_Bm  [BL_ * DS_];
__device__ float g_dt  [BL_ * DI_];
__device__ float g_ypart[NQD * BL_ * DS_];  // partial y per d-chunk
__device__ float g_negA[DI_ * DS_];
// transposed weights: tW[k*N + n] = W[n*K + k]
__device__ float g_tinW [DM_ * 512];   // 128 x 512
__device__ float g_txW  [DI_ * DS_];   // 256 x 256 (first DS rows of x_proj_w)
__device__ float g_tdtW [DI_ * DI_];   // 256 x 256
__device__ float g_toutW[DI_ * DM_];   // 256 x 128

// ---------------------------------------------------------------------------
// prep: blockIdx.y 0..3 -> transpose one weight matrix; y==4 -> negA
__global__ void k_prep(const float* __restrict__ inW,
                       const float* __restrict__ xW,
                       const float* __restrict__ dtW,
                       const float* __restrict__ outW,
                       const float* __restrict__ A_log) {
    if (blockIdx.y == 4) {
        int tid = threadIdx.y * 32 + threadIdx.x;       // 0..255
        for (int i = blockIdx.x * 256 + tid; i < DI_ * DS_; i += 64 * 256)
            g_negA[i] = -__expf(A_log[i]);
        return;
    }
    __shared__ float tile[32][33];
    const float* src; float* dst; int R, Ccol;   // src is R x Ccol
    switch (blockIdx.y) {
        case 0: src = inW;  dst = g_tinW;  R = 512; Ccol = DM_; break;
        case 1: src = xW;   dst = g_txW;   R = DS_; Ccol = DI_; break;
        case 2: src = dtW;  dst = g_tdtW;  R = DI_; Ccol = DI_; break;
        default:src = outW; dst = g_toutW; R = DM_; Ccol = DI_; break;
    }
    int tilesX = Ccol >> 5;
    int tx = blockIdx.x % tilesX;
    int ty = blockIdx.x / tilesX;
    if (ty >= (R >> 5)) return;
    int c = tx * 32 + threadIdx.x;
    int r = ty * 32 + threadIdx.y;
    #pragma unroll
    for (int j = 0; j < 32; j += 8)
        tile[threadIdx.y + j][threadIdx.x] = src[(r + j) * Ccol + c];
    __syncthreads();
    int oc = ty * 32 + threadIdx.x;
    int orow = tx * 32 + threadIdx.y;
    #pragma unroll
    for (int j = 0; j < 32; j += 8)
        dst[(orow + j) * R + oc] = tile[threadIdx.x][threadIdx.y + j];
}

// ---------------------------------------------------------------------------
// in_proj: grid (200 rowpairs, 4 colgroups), 256 threads = 128 cols x 2 k-halves
__global__ void k_inproj(const float* __restrict__ hs,
                         const float* __restrict__ bias) {
    __shared__ float sh[2][DM_];
    __shared__ float spart[2][2][128];
    int r0 = blockIdx.x * 2;
    int cg = blockIdx.y;
    int t  = threadIdx.x;            // 0..255
    {
        int r = t >> 7, k = t & 127;
        sh[r][k] = hs[(r0 + r) * DM_ + k];
    }
    __syncthreads();

    int cl = t & 127;
    int col = cg * 128 + cl;         // 0..511
    int kh = t >> 7;                 // 0..1
    float a0 = 0.f, a1 = 0.f;
    #pragma unroll 16
    for (int kk = 0; kk < 64; kk++) {
        int k = kh * 64 + kk;
        float wv = g_tinW[k * 512 + col];
        a0 = fmaf(wv, sh[0][k], a0);
        a1 = fmaf(wv, sh[1][k], a1);
    }
    spart[kh][0][cl] = a0;
    spart[kh][1][cl] = a1;
    __syncthreads();

    if (kh == 0) {
        float bv = __ldg(bias + col);
        float v0 = spart[0][0][cl] + spart[1][0][cl] + bv;
        float v1 = spart[0][1][cl] + spart[1][1][cl] + bv;
        if (col < DI_) {
            g_xpre[(r0 + 0) * DI_ + col] = v0;
            g_xpre[(r0 + 1) * DI_ + col] = v1;
        } else {
            int j = col - DI_;
            g_z[(r0 + 0) * DI_ + j] = v0;
            g_z[(r0 + 1) * DI_ + j] = v1;
        }
    }
}

// ---------------------------------------------------------------------------
// fused conv+silu (recomputed per colgroup; only cg0 writes g_x), then
// Bm / softplus-dt GEMM. grid (200 rowpairs, 4 colgroups),
// 256 threads = 128 cols x 2 k-halves.
__global__ void k_convxprojdt(const float* __restrict__ cw,
                              const float* __restrict__ cb,
                              const float* __restrict__ dtb) {
    __shared__ float sx[2][DI_];
    __shared__ float spart[2][2][128];
    int r0 = blockIdx.x * 2;
    int cg = blockIdx.y;
    int b  = r0 / L_;
    int l0 = r0 - b * L_;
    int t  = threadIdx.x;            // 0..255

    // conv + silu for the 2 rows (512 items, 2 per thread)
    #pragma unroll
    for (int i = t; i < 2 * DI_; i += 256) {
        int r = i >> 8, c = i & 255;
        int l = l0 + r;
        float acc = __ldg(cb + c);
        #pragma unroll
        for (int j = 0; j < 4; j++) {
            int ll = l - 3 + j;
            if (ll >= 0)
                acc = fmaf(__ldg(cw + c * 4 + j), g_xpre[(b * L_ + ll) * DI_ + c], acc);
        }
        float sg = 1.f / (1.f + __expf(-acc));
        float xv = acc * sg;
        sx[r][c] = xv;
        if (cg == 0) g_x[(r0 + r) * DI_ + c] = xv;
    }
    __syncthreads();

    int cl = t & 127;
    int col = cg * 128 + cl;         // 0..511
    int kh = t >> 7;                 // 0..1
    const float* wr = (col < DS_) ? (g_txW + col) : (g_tdtW + (col - DS_));
    float a0 = 0.f, a1 = 0.f;
    #pragma unroll 16
    for (int kk = 0; kk < 128; kk++) {
        int k = kh * 128 + kk;
        float wv = wr[k * DI_];
        a0 = fmaf(wv, sx[0][k], a0);
        a1 = fmaf(wv, sx[1][k], a1);
    }
    spart[kh][0][cl] = a0;
    spart[kh][1][cl] = a1;
    __syncthreads();

    if (kh == 0) {
        float v0 = spart[0][0][cl] + spart[1][0][cl];
        float v1 = spart[0][1][cl] + spart[1][1][cl];
        if (col < DS_) {
            g_Bm[(r0 + 0) * DS_ + col] = v0;
            g_Bm[(r0 + 1) * DS_ + col] = v1;
        } else {
            int j = col - DS_;
            float bv = __ldg(dtb + j);
            float v, sp;
            v = v0 + bv; sp = (v > 15.f) ? v : log1pf(__expf(v)); g_dt[(r0 + 0) * DI_ + j] = sp;
            v = v1 + bv; sp = (v > 15.f) ? v : log1pf(__expf(v)); g_dt[(r0 + 1) * DI_ + j] = sp;
        }
    }
}

// ---------------------------------------------------------------------------
// main (R6 verbatim): 6400 blocks = (l, qd, b) with b fastest; 256 threads =
// 4 d-subgroups x 64 float4 n-lanes, 4 d's per subgroup (16 d per block).
//   as[d,n] = state[b,l,d,n]*exp(dt[d]*negA[d,n]) + dt[d]*Bm[n]
//   ypart[qd][b,l,n] = sum_{d in chunk qd} as[d,n] * C[l,d,n]
__global__ void __launch_bounds__(256, 6) k_main(
        const float* __restrict__ state,
        const float* __restrict__ C,
        float*       __restrict__ out_state) {
    int bid = blockIdx.x;
    int b  = bid & 3;
    int qd = (bid >> 2) & (NQD - 1);
    int l  = bid >> 6;                // 0..99
    int blr = b * L_ + l;
    int t  = threadIdx.x;             // 0..255
    int g  = t >> 6;                  // subgroup 0..3
    int nq = t & 63;                  // float4 lane over n

    __shared__ float sdt[16];         // dt for this chunk
    if (t < 16) sdt[t] = g_dt[blr * DI_ + qd * 16 + t];
    __syncthreads();

    float4 bm = ((const float4*)(g_Bm + (size_t)blr * DS_))[nq];

    size_t rowbase  = (size_t)blr * DI_ * DS_;
    size_t crowbase = (size_t)l * DI_ * DS_;
    int d0 = qd * 16 + g * 4;

    float4 acc = make_float4(0.f, 0.f, 0.f, 0.f);
    #pragma unroll
    for (int dd = 0; dd < 4; dd++) {
        int d = d0 + dd;
        const float4* s4  = (const float4*)(state + rowbase + (size_t)d * DS_);
        const float4* c4  = (const float4*)(C + crowbase + (size_t)d * DS_);
        const float4* na4 = (const float4*)(g_negA + (size_t)d * DS_);
        float4*       o4  = (float4*)(out_state + rowbase + (size_t)d * DS_);
        float  dt = sdt[d - qd * 16];
        float4 s  = __ldcs(s4 + nq);
        float4 na = __ldg(na4 + nq);
        float4 c  = __ldg(c4 + nq);
        float4 as;
        as.x = fmaf(s.x, __expf(dt * na.x), dt * bm.x);
        as.y = fmaf(s.y, __expf(dt * na.y), dt * bm.y);
        as.z = fmaf(s.z, __expf(dt * na.z), dt * bm.z);
        as.w = fmaf(s.w, __expf(dt * na.w), dt * bm.w);
        __stcs(o4 + nq, as);
        acc.x = fmaf(as.x, c.x, acc.x);
        acc.y = fmaf(as.y, c.y, acc.y);
        acc.z = fmaf(as.z, c.z, acc.z);
        acc.w = fmaf(as.w, c.w, acc.w);
    }

    __shared__ float4 racc[4][64];
    racc[g][nq] = acc;
    __syncthreads();

    if (g == 0) {
        float4 a0 = racc[0][nq], a1 = racc[1][nq],
               a2 = racc[2][nq], a3 = racc[3][nq];
        float4 tot;
        tot.x = (a0.x + a1.x) + (a2.x + a3.x);
        tot.y = (a0.y + a1.y) + (a2.y + a3.y);
        tot.z = (a0.z + a1.z) + (a2.z + a3.z);
        tot.w = (a0.w + a1.w) + (a2.w + a3.w);
        ((float4*)(g_ypart + (size_t)qd * BL_ * DS_ + (size_t)blr * DS_))[nq] = tot;
    }
}

// ---------------------------------------------------------------------------
// out = y @ out_proj_w^T + b with fused epilogue. grid (200 rowpairs, 2
// colgroups), 256 threads = 64 cols x 4 k-quarters (k=64 each).
__global__ void k_outproj(const float* __restrict__ D1,
                          const float* __restrict__ bias,
                          float* __restrict__ out) {
    __shared__ float sh[2][DI_];
    __shared__ float spart[4][2][64];
    int r0 = blockIdx.x * 2;
    int cg = blockIdx.y;
    int t  = threadIdx.x;            // 0..255

    for (int i = t; i < 2 * DI_; i += 256) {
        int r = i >> 8, k = i & 255;
        int idx = (r0 + r) * DI_ + k;
        float tot = 0.f;
        #pragma unroll
        for (int qq = 0; qq < NQD; qq++)
            tot += g_ypart[qq * (BL_ * DS_) + idx];
        float xv = g_x[idx];
        float zv = g_z[idx];
        float y  = fmaf(__ldg(D1 + k), xv, tot);
        float sg = 1.f / (1.f + __expf(-zv));
        sh[r][k] = y * (zv * sg);
    }
    __syncthreads();

    int cl = t & 63;
    int col = cg * 64 + cl;          // 0..127
    int kq = t >> 6;                 // 0..3
    float a0 = 0.f, a1 = 0.f;
    #pragma unroll 16
    for (int kk = 0; kk < 64; kk++) {
        int k = kq * 64 + kk;
        float wv = g_toutW[k * DM_ + col];
        a0 = fmaf(wv, sh[0][k], a0);
        a1 = fmaf(wv, sh[1][k], a1);
    }
    spart[kq][0][cl] = a0;
    spart[kq][1][cl] = a1;
    __syncthreads();

    if (kq == 0) {
        float bv = __ldg(bias + col);
        float v0 = (spart[0][0][cl] + spart[1][0][cl]) + (spart[2][0][cl] + spart[3][0][cl]) + bv;
        float v1 = (spart[0][1][cl] + spart[1][1][cl]) + (spart[2][1][cl] + spart[3][1][cl]) + bv;
        out[(r0 + 0) * DM_ + col] = v0;
        out[(r0 + 1) * DM_ + col] = v1;
    }
}

// ---------------------------------------------------------------------------
extern "C" void kernel_launch(void* const* d_in, const int* in_sizes, int n_in,
                              void* d_out, int out_size) {
    const float* hs      = (const float*)d_in[0];   // (4,100,128)
    const float* state   = (const float*)d_in[1];   // (4,100,256,256)
    const float* inW     = (const float*)d_in[2];   // (512,128)
    const float* inB     = (const float*)d_in[3];   // (512,)
    const float* convW   = (const float*)d_in[4];   // (256,1,4)
    const float* convB   = (const float*)d_in[5];   // (256,)
    const float* xW      = (const float*)d_in[6];   // (512,256)
    const float* dtW     = (const float*)d_in[7];   // (256,256)
    const float* dtB     = (const float*)d_in[8];   // (256,)
    const float* A_log   = (const float*)d_in[9];   // (256,256)
    const float* D1      = (const float*)d_in[10];  // (256,)
    const float* Cp      = (const float*)d_in[11];  // (100,256,256)
    const float* outW    = (const float*)d_in[12];  // (128,256)
    const float* outB    = (const float*)d_in[13];  // (128,)

    float* out       = (float*)d_out;               // (4,100,128) first
    float* out_state = out + B_ * L_ * DM_;         // then (4,100,256,256)

    k_prep        <<<dim3(64, 5), dim3(32, 8)>>>(inW, xW, dtW, outW, A_log);
    k_inproj      <<<dim3(BL_ / 2, 4), 256>>>(hs, inB);
    k_convxprojdt <<<dim3(BL_ / 2, 4), 256>>>(convW, convB, dtB);
    k_main        <<<BL_ * NQD, 256>>>(state, Cp, out_state);   // 4th (profiled)
    k_outproj     <<<dim3(BL_ / 2, 2), 256>>>(D1, outB, out);
}

// round 10
// speedup vs baseline: 1.6722x; 1.0672x over previous
#include <cuda_runtime.h>

#define B_  4
#define L_  100
#define BL_ 400           // B*L
#define DM_ 128           // d_model
#define DI_ 256           // d_inner
#define DS_ 256           // d_state
#define NQD 16            // d-chunks in k_main (16 d's each)

// scratch (device globals; no allocations allowed)
__device__ float g_xpre[BL_ * DI_];
__device__ float g_x   [BL_ * DI_];
__device__ float g_z   [BL_ * DI_];
__device__ float g_Bm  [BL_ * DS_];
__device__ float g_dt  [BL_ * DI_];
__device__ float g_ypart[NQD * BL_ * DS_];  // partial y per d-chunk
__device__ float g_negA[DI_ * DS_];         // -exp(A_log) * log2(e)
// transposed weights: tW[k*N + n] = W[n*K + k]
__device__ float g_tinW [DM_ * 512];   // 128 x 512
__device__ float g_txW  [DI_ * DS_];   // 256 x 256 (first DS rows of x_proj_w)
__device__ float g_tdtW [DI_ * DI_];   // 256 x 256
__device__ float g_toutW[DI_ * DM_];   // 256 x 128

#define LOG2E 1.4426950408889634f

// ---------------------------------------------------------------------------
// prep: blockIdx.y 0..3 -> transpose one weight matrix; y==4 -> negA
__global__ void k_prep(const float* __restrict__ inW,
                       const float* __restrict__ xW,
                       const float* __restrict__ dtW,
                       const float* __restrict__ outW,
                       const float* __restrict__ A_log) {
    if (blockIdx.y == 4) {
        int tid = threadIdx.y * 32 + threadIdx.x;       // 0..255
        for (int i = blockIdx.x * 256 + tid; i < DI_ * DS_; i += 64 * 256)
            g_negA[i] = -__expf(A_log[i]) * LOG2E;
        return;
    }
    __shared__ float tile[32][33];
    const float* src; float* dst; int R, Ccol;   // src is R x Ccol
    switch (blockIdx.y) {
        case 0: src = inW;  dst = g_tinW;  R = 512; Ccol = DM_; break;
        case 1: src = xW;   dst = g_txW;   R = DS_; Ccol = DI_; break;
        case 2: src = dtW;  dst = g_tdtW;  R = DI_; Ccol = DI_; break;
        default:src = outW; dst = g_toutW; R = DM_; Ccol = DI_; break;
    }
    int tilesX = Ccol >> 5;
    int tx = blockIdx.x % tilesX;
    int ty = blockIdx.x / tilesX;
    if (ty >= (R >> 5)) return;
    int c = tx * 32 + threadIdx.x;
    int r = ty * 32 + threadIdx.y;
    #pragma unroll
    for (int j = 0; j < 32; j += 8)
        tile[threadIdx.y + j][threadIdx.x] = src[(r + j) * Ccol + c];
    __syncthreads();
    int oc = ty * 32 + threadIdx.x;
    int orow = tx * 32 + threadIdx.y;
    #pragma unroll
    for (int j = 0; j < 32; j += 8)
        dst[(orow + j) * R + oc] = tile[threadIdx.x][threadIdx.y + j];
}

// ---------------------------------------------------------------------------
// in_proj: grid (200 rowpairs, 4 colgroups), 256 threads = 128 cols x 2 k-halves
__global__ void k_inproj(const float* __restrict__ hs,
                         const float* __restrict__ bias) {
    __shared__ float sh[2][DM_];
    __shared__ float spart[2][2][128];
    int r0 = blockIdx.x * 2;
    int cg = blockIdx.y;
    int t  = threadIdx.x;            // 0..255
    {
        int r = t >> 7, k = t & 127;
        sh[r][k] = hs[(r0 + r) * DM_ + k];
    }
    __syncthreads();

    int cl = t & 127;
    int col = cg * 128 + cl;         // 0..511
    int kh = t >> 7;                 // 0..1
    float a0 = 0.f, a1 = 0.f;
    #pragma unroll 16
    for (int kk = 0; kk < 64; kk++) {
        int k = kh * 64 + kk;
        float wv = g_tinW[k * 512 + col];
        a0 = fmaf(wv, sh[0][k], a0);
        a1 = fmaf(wv, sh[1][k], a1);
    }
    spart[kh][0][cl] = a0;
    spart[kh][1][cl] = a1;
    __syncthreads();

    if (kh == 0) {
        float bv = __ldg(bias + col);
        float v0 = spart[0][0][cl] + spart[1][0][cl] + bv;
        float v1 = spart[0][1][cl] + spart[1][1][cl] + bv;
        if (col < DI_) {
            g_xpre[(r0 + 0) * DI_ + col] = v0;
            g_xpre[(r0 + 1) * DI_ + col] = v1;
        } else {
            int j = col - DI_;
            g_z[(r0 + 0) * DI_ + j] = v0;
            g_z[(r0 + 1) * DI_ + j] = v1;
        }
    }
}

// ---------------------------------------------------------------------------
// fused conv+silu (recomputed per colgroup; only cg0 writes g_x), then
// Bm / softplus-dt GEMM. grid (200 rowpairs, 4 colgroups),
// 256 threads = 128 cols x 2 k-halves.
__global__ void k_convxprojdt(const float* __restrict__ cw,
                              const float* __restrict__ cb,
                              const float* __restrict__ dtb) {
    __shared__ float sx[2][DI_];
    __shared__ float spart[2][2][128];
    int r0 = blockIdx.x * 2;
    int cg = blockIdx.y;
    int b  = r0 / L_;
    int l0 = r0 - b * L_;
    int t  = threadIdx.x;            // 0..255

    #pragma unroll
    for (int i = t; i < 2 * DI_; i += 256) {
        int r = i >> 8, c = i & 255;
        int l = l0 + r;
        float acc = __ldg(cb + c);
        #pragma unroll
        for (int j = 0; j < 4; j++) {
            int ll = l - 3 + j;
            if (ll >= 0)
                acc = fmaf(__ldg(cw + c * 4 + j), g_xpre[(b * L_ + ll) * DI_ + c], acc);
        }
        float sg = 1.f / (1.f + __expf(-acc));
        float xv = acc * sg;
        sx[r][c] = xv;
        if (cg == 0) g_x[(r0 + r) * DI_ + c] = xv;
    }
    __syncthreads();

    int cl = t & 127;
    int col = cg * 128 + cl;         // 0..511
    int kh = t >> 7;                 // 0..1
    const float* wr = (col < DS_) ? (g_txW + col) : (g_tdtW + (col - DS_));
    float a0 = 0.f, a1 = 0.f;
    #pragma unroll 16
    for (int kk = 0; kk < 128; kk++) {
        int k = kh * 128 + kk;
        float wv = wr[k * DI_];
        a0 = fmaf(wv, sx[0][k], a0);
        a1 = fmaf(wv, sx[1][k], a1);
    }
    spart[kh][0][cl] = a0;
    spart[kh][1][cl] = a1;
    __syncthreads();

    if (kh == 0) {
        float v0 = spart[0][0][cl] + spart[1][0][cl];
        float v1 = spart[0][1][cl] + spart[1][1][cl];
        if (col < DS_) {
            g_Bm[(r0 + 0) * DS_ + col] = v0;
            g_Bm[(r0 + 1) * DS_ + col] = v1;
        } else {
            int j = col - DS_;
            float bv = __ldg(dtb + j);
            float v, sp;
            v = v0 + bv; sp = (v > 15.f) ? v : log1pf(__expf(v)); g_dt[(r0 + 0) * DI_ + j] = sp;
            v = v1 + bv; sp = (v > 15.f) ? v : log1pf(__expf(v)); g_dt[(r0 + 1) * DI_ + j] = sp;
        }
    }
}

// ---------------------------------------------------------------------------
// main: 6400 blocks = (l, qd, b) with b fastest; 256 threads =
// 4 d-subgroups x 64 float4 n-lanes, 4 d's per subgroup (16 d per block).
// All 4 streaming state loads hoisted ahead of the compute loop (MLP);
// negA is prescaled by log2(e) so the exp path is a single MUFU.EX2.
__global__ void __launch_bounds__(256, 5) k_main(
        const float* __restrict__ state,
        const float* __restrict__ C,
        float*       __restrict__ out_state) {
    int bid = blockIdx.x;
    int b  = bid & 3;
    int qd = (bid >> 2) & (NQD - 1);
    int l  = bid >> 6;                // 0..99
    int blr = b * L_ + l;
    int t  = threadIdx.x;             // 0..255
    int g  = t >> 6;                  // subgroup 0..3
    int nq = t & 63;                  // float4 lane over n

    __shared__ float sdt[16];         // dt for this chunk
    if (t < 16) sdt[t] = g_dt[blr * DI_ + qd * 16 + t];
    __syncthreads();

    float4 bm = ((const float4*)(g_Bm + (size_t)blr * DS_))[nq];

    size_t rowbase  = (size_t)blr * DI_ * DS_;
    size_t crowbase = (size_t)l * DI_ * DS_;
    int d0 = qd * 16 + g * 4;

    // hoist all 4 streaming state loads (deep MLP)
    float4 s[4];
    #pragma unroll
    for (int dd = 0; dd < 4; dd++)
        s[dd] = __ldcs((const float4*)(state + rowbase + (size_t)(d0 + dd) * DS_) + nq);

    float4 acc = make_float4(0.f, 0.f, 0.f, 0.f);
    #pragma unroll
    for (int dd = 0; dd < 4; dd++) {
        int d = d0 + dd;
        float4 na = __ldg((const float4*)(g_negA + (size_t)d * DS_) + nq);
        float4 c  = __ldg((const float4*)(C + crowbase + (size_t)d * DS_) + nq);
        float  dt = sdt[d - qd * 16];
        float4 as;
        as.x = fmaf(s[dd].x, exp2f(dt * na.x), dt * bm.x);
        as.y = fmaf(s[dd].y, exp2f(dt * na.y), dt * bm.y);
        as.z = fmaf(s[dd].z, exp2f(dt * na.z), dt * bm.z);
        as.w = fmaf(s[dd].w, exp2f(dt * na.w), dt * bm.w);
        __stcs((float4*)(out_state + rowbase + (size_t)d * DS_) + nq, as);
        acc.x = fmaf(as.x, c.x, acc.x);
        acc.y = fmaf(as.y, c.y, acc.y);
        acc.z = fmaf(as.z, c.z, acc.z);
        acc.w = fmaf(as.w, c.w, acc.w);
    }

    __shared__ float4 racc[4][64];
    racc[g][nq] = acc;
    __syncthreads();

    if (g == 0) {
        float4 a0 = racc[0][nq], a1 = racc[1][nq],
               a2 = racc[2][nq], a3 = racc[3][nq];
        float4 tot;
        tot.x = (a0.x + a1.x) + (a2.x + a3.x);
        tot.y = (a0.y + a1.y) + (a2.y + a3.y);
        tot.z = (a0.z + a1.z) + (a2.z + a3.z);
        tot.w = (a0.w + a1.w) + (a2.w + a3.w);
        ((float4*)(g_ypart + (size_t)qd * BL_ * DS_ + (size_t)blr * DS_))[nq] = tot;
    }
}

// ---------------------------------------------------------------------------
// out = y @ out_proj_w^T + b with fused epilogue. grid (200 rowpairs, 2
// colgroups), 256 threads = 64 cols x 4 k-quarters (k=64 each).
__global__ void k_outproj(const float* __restrict__ D1,
                          const float* __restrict__ bias,
                          float* __restrict__ out) {
    __shared__ float sh[2][DI_];
    __shared__ float spart[4][2][64];
    int r0 = blockIdx.x * 2;
    int cg = blockIdx.y;
    int t  = threadIdx.x;            // 0..255

    for (int i = t; i < 2 * DI_; i += 256) {
        int r = i >> 8, k = i & 255;
        int idx = (r0 + r) * DI_ + k;
        float tot = 0.f;
        #pragma unroll
        for (int qq = 0; qq < NQD; qq++)
            tot += g_ypart[qq * (BL_ * DS_) + idx];
        float xv = g_x[idx];
        float zv = g_z[idx];
        float y  = fmaf(__ldg(D1 + k), xv, tot);
        float sg = 1.f / (1.f + __expf(-zv));
        sh[r][k] = y * (zv * sg);
    }
    __syncthreads();

    int cl = t & 63;
    int col = cg * 64 + cl;          // 0..127
    int kq = t >> 6;                 // 0..3
    float a0 = 0.f, a1 = 0.f;
    #pragma unroll 16
    for (int kk = 0; kk < 64; kk++) {
        int k = kq * 64 + kk;
        float wv = g_toutW[k * DM_ + col];
        a0 = fmaf(wv, sh[0][k], a0);
        a1 = fmaf(wv, sh[1][k], a1);
    }
    spart[kq][0][cl] = a0;
    spart[kq][1][cl] = a1;
    __syncthreads();

    if (kq == 0) {
        float bv = __ldg(bias + col);
        float v0 = (spart[0][0][cl] + spart[1][0][cl]) + (spart[2][0][cl] + spart[3][0][cl]) + bv;
        float v1 = (spart[0][1][cl] + spart[1][1][cl]) + (spart[2][1][cl] + spart[3][1][cl]) + bv;
        out[(r0 + 0) * DM_ + col] = v0;
        out[(r0 + 1) * DM_ + col] = v1;
    }
}

// ---------------------------------------------------------------------------
extern "C" void kernel_launch(void* const* d_in, const int* in_sizes, int n_in,
                              void* d_out, int out_size) {
    const float* hs      = (const float*)d_in[0];   // (4,100,128)
    const float* state   = (const float*)d_in[1];   // (4,100,256,256)
    const float* inW     = (const float*)d_in[2];   // (512,128)
    const float* inB     = (const float*)d_in[3];   // (512,)
    const float* convW   = (const float*)d_in[4];   // (256,1,4)
    const float* convB   = (const float*)d_in[5];   // (256,)
    const float* xW      = (const float*)d_in[6];   // (512,256)
    const float* dtW     = (const float*)d_in[7];   // (256,256)
    const float* dtB     = (const float*)d_in[8];   // (256,)
    const float* A_log   = (const float*)d_in[9];   // (256,256)
    const float* D1      = (const float*)d_in[10];  // (256,)
    const float* Cp      = (const float*)d_in[11];  // (100,256,256)
    const float* outW    = (const float*)d_in[12];  // (128,256)
    const float* outB    = (const float*)d_in[13];  // (128,)

    float* out       = (float*)d_out;               // (4,100,128) first
    float* out_state = out + B_ * L_ * DM_;         // then (4,100,256,256)

    k_prep        <<<dim3(64, 5), dim3(32, 8)>>>(inW, xW, dtW, outW, A_log);
    k_inproj      <<<dim3(BL_ / 2, 4), 256>>>(hs, inB);
    k_convxprojdt <<<dim3(BL_ / 2, 4), 256>>>(convW, convB, dtB);
    k_main        <<<BL_ * NQD, 256>>>(state, Cp, out_state);   // 4th (profiled)
    k_outproj     <<<dim3(BL_ / 2, 2), 256>>>(D1, outB, out);
}